// round 6
// baseline (speedup 1.0000x reference)
#include <cuda_runtime.h>
#include <cuda_bf16.h>

// Problem constants (fixed by setup_inputs)
#define Bn 4
#define Cn 32
#define Hn 128
#define Wn 128
#define Kn 128
#define Vn 16          // Cn/2 vertices per polygon
#define HWn (Hn * Wn)
#define BKn (Bn * Kn)  // 512

// Scratch (no device allocation allowed -> __device__ globals)
__device__ float        g_iou_m[BKn];
__device__ unsigned int g_done;        // zero-initialized; reset by last block

typedef unsigned long long ull;

// ~0ull >> n with PTX clamp semantics: n >= 64 -> 0
__device__ __forceinline__ ull shr64c(int n) {
    ull r;
    asm("shr.u64 %0, %1, %2;" : "=l"(r) : "l"(~0ULL), "r"(n));
    return r;
}

__global__ void __launch_bounds__(512)
iou_fused_kernel(const float* __restrict__ out4d,   // [B,C,H,W]
                 const int*   __restrict__ mask,    // [B,K]
                 const int*   __restrict__ ind,     // [B,K]
                 const float* __restrict__ target,  // [B,C,K]
                 float*       __restrict__ loss)    // [1]
{
    const int bk  = blockIdx.x;
    const int b   = bk >> 7;            // / Kn
    const int k   = bk & (Kn - 1);
    const int tid = threadIdx.x;        // 0..511
    const int h   = tid >> 8;           // edge half: 0 -> edges 0..7, 1 -> 8..15
    const int p   = (tid >> 7) & 1;     // 0 = pred, 1 = gt
    const int row = tid & 127;          // scanline

    // One float4 per edge: (y1, slope, x1, bitcast(ymin | range<<16))
    __shared__ float4 edge[2][Vn];
    __shared__ ull    s_lo[2][128], s_hi[2][128];   // h==1 partial masks
    __shared__ ull    s_glo[128],   s_ghi[128];     // combined gt masks

    // ---- warp 0: load vertices, exchange via shfl, build edge params ----
    if (tid < 32) {
        const int pv = tid >> 4;        // 0 = pred, 1 = gt
        const int v  = tid & 15;
        float x, y;
        if (pv == 0) {
            const int idx = ind[bk];
            x = out4d[(size_t)(b * Cn + 2 * v)     * HWn + idx];
            y = out4d[(size_t)(b * Cn + 2 * v + 1) * HWn + idx];
        } else {
            x = target[(size_t)(b * Cn + 2 * v)     * Kn + k];
            y = target[(size_t)(b * Cn + 2 * v + 1) * Kn + k];
        }
        const float x1 = truncf(x) + 100.0f;
        const float y1 = truncf(y) + 100.0f;
        const int nxt = (pv << 4) | ((v + 1) & 15);
        const float x2 = __shfl_sync(0xFFFFFFFFu, x1, nxt);
        const float y2 = __shfl_sync(0xFFFFFFFFu, y1, nxt);
        const float d  = y2 - y1;
        const float s  = __fdividef(x2 - x1, d);   // inf/NaN when d==0: never crossed
        const int iymin = (int)fminf(y1, y2);
        const int iymax = (int)fmaxf(y1, y2);
        const int pk = iymin | ((iymax - iymin) << 16);
        edge[pv][v] = make_float4(y1, s, x1, __int_as_float(pk));
    }
    __syncthreads();

    // ---- rasterize my 8 edges of my polygon at my row: XOR of prefix masks --
    const float py = (float)row;
    ull lo = 0, hi = 0;
#pragma unroll
    for (int vv = 0; vv < Vn / 2; vv++) {
        const float4 e = edge[p][h * (Vn / 2) + vv];
        const int pk = __float_as_int(e.w);
        const bool crosses = (unsigned)(row - (pk & 0xFFFF)) < (unsigned)(pk >> 16);
        const float xint = fmaf(py - e.x, e.y, e.z);
        // crossing x-intersections lie in [10,121]; sentinel m=0 -> both masks 0
        const int m = crosses ? __float2int_ru(xint) : 0;
        lo ^= shr64c(64  - min(m, 64));   // low  m bits (saturating)
        hi ^= shr64c(128 - max(m, 64));   // bits [64, m)
    }

    // ---- combine halves, publish gt, popc ----
    if (h == 1) { s_lo[p][row] = lo; s_hi[p][row] = hi; }
    __syncthreads();

    int my_area = 0, my_inter = 0;
    if (h == 0) {
        lo ^= s_lo[p][row];
        hi ^= s_hi[p][row];
        my_area = __popcll(lo) + __popcll(hi);
        if (p == 1) { s_glo[row] = lo; s_ghi[row] = hi; }
    }
    __syncthreads();
    if (h == 0 && p == 0)
        my_inter = __popcll(lo & s_glo[row]) + __popcll(hi & s_ghi[row]);

    // ---- block reduce (512 threads = 16 warps) ----
    __shared__ int s_i[16], s_a[16];
#pragma unroll
    for (int off = 16; off > 0; off >>= 1) {
        my_inter += __shfl_down_sync(0xFFFFFFFFu, my_inter, off);
        my_area  += __shfl_down_sync(0xFFFFFFFFu, my_area,  off);
    }
    const int warp = tid >> 5;
    const int lane = tid & 31;
    if (lane == 0) { s_i[warp] = my_inter; s_a[warp] = my_area; }
    __syncthreads();

    __shared__ int s_last;
    if (tid == 0) {
        int I = 0, PG = 0;
#pragma unroll
        for (int w = 0; w < 16; w++) { I += s_i[w]; PG += s_a[w]; }
        const float interf = (float)I;
        const float unionf = (float)PG - interf;
        const float iou = interf / (unionf + 0.0001f);
        g_iou_m[bk] = iou * (float)mask[bk];
        __threadfence();
        const unsigned int c = atomicAdd(&g_done, 1u);
        s_last = (c == (unsigned int)(BKn - 1));
    }
    __syncthreads();

    // ---- last block: deterministic final reduction (512 thr, 512 elems) ----
    if (s_last) {
        float num = g_iou_m[tid];
        float den = (float)mask[tid];
        __shared__ float r_n[16], r_d[16];
#pragma unroll
        for (int off = 16; off > 0; off >>= 1) {
            num += __shfl_down_sync(0xFFFFFFFFu, num, off);
            den += __shfl_down_sync(0xFFFFFFFFu, den, off);
        }
        if (lane == 0) { r_n[warp] = num; r_d[warp] = den; }
        __syncthreads();
        if (tid == 0) {
            float N = 0.0f, D = 0.0f;
#pragma unroll
            for (int w = 0; w < 16; w++) { N += r_n[w]; D += r_d[w]; }
            loss[0] = 1.0f - N / (D + 0.0001f);
            g_done = 0;   // reset for next graph replay
        }
    }
}

extern "C" void kernel_launch(void* const* d_in, const int* in_sizes, int n_in,
                              void* d_out, int out_size) {
    const float* out4d  = (const float*)d_in[0];   // output  [B,C,H,W]
    const int*   mask   = (const int*)  d_in[1];   // mask    [B,K]
    const int*   ind    = (const int*)  d_in[2];   // ind     [B,K]
    const float* target = (const float*)d_in[3];   // target  [B,C,K]
    float* loss = (float*)d_out;

    iou_fused_kernel<<<BKn, 512>>>(out4d, mask, ind, target, loss);
}

// round 10
// speedup vs baseline: 1.8413x; 1.8413x over previous
#include <cuda_runtime.h>
#include <cuda_bf16.h>

// Problem constants (fixed by setup_inputs)
#define Bn 4
#define Cn 32
#define Hn 128
#define Wn 128
#define Kn 128
#define Vn 16          // Cn/2 vertices per polygon
#define HWn (Hn * Wn)
#define BKn (Bn * Kn)  // 512

// Accumulators (no device allocation allowed -> __device__ globals, zero-init)
__device__ unsigned long long g_num;   // sum(iou*mask) in 32.32 fixed point
__device__ unsigned int       g_den;   // sum(mask)
__device__ unsigned int       g_done;  // completion counter

typedef unsigned long long ull;

// ~0ull >> n with PTX clamp semantics: n >= 64 -> 0
__device__ __forceinline__ ull shr64c(int n) {
    ull r;
    asm("shr.u64 %0, %1, %2;" : "=l"(r) : "l"(~0ULL), "r"(n));
    return r;
}

__global__ void __launch_bounds__(256)
iou_fused_kernel(const float* __restrict__ out4d,   // [B,C,H,W]
                 const int*   __restrict__ mask,    // [B,K]
                 const int*   __restrict__ ind,     // [B,K]
                 const float* __restrict__ target,  // [B,C,K]
                 float*       __restrict__ loss)    // [1]
{
    const int bk  = blockIdx.x;
    const int b   = bk >> 7;            // / Kn
    const int k   = bk & (Kn - 1);
    const int tid = threadIdx.x;        // 0..255
    const int p   = tid >> 7;           // 0 = pred, 1 = gt
    const int row = tid & 127;          // scanline

    // One float4 per edge: (y1, slope, x1, bitcast(ymin | range<<16))
    __shared__ float4 edge[2][Vn];
    __shared__ ull    s_glo[128], s_ghi[128];

    // ---- warp 0: load vertices, exchange via shfl, build edge params ----
    if (tid < 32) {
        const int pv = tid >> 4;        // 0 = pred, 1 = gt
        const int v  = tid & 15;
        float x, y;
        if (pv == 0) {
            const int idx = ind[bk];
            x = out4d[(size_t)(b * Cn + 2 * v)     * HWn + idx];
            y = out4d[(size_t)(b * Cn + 2 * v + 1) * HWn + idx];
        } else {
            x = target[(size_t)(b * Cn + 2 * v)     * Kn + k];
            y = target[(size_t)(b * Cn + 2 * v + 1) * Kn + k];
        }
        const float x1 = truncf(x) + 100.0f;
        const float y1 = truncf(y) + 100.0f;
        const int nxt = (pv << 4) | ((v + 1) & 15);
        const float x2 = __shfl_sync(0xFFFFFFFFu, x1, nxt);
        const float y2 = __shfl_sync(0xFFFFFFFFu, y1, nxt);
        const float d  = y2 - y1;
        const float s  = __fdividef(x2 - x1, d);   // inf/NaN when d==0: never crossed
        const int iymin = (int)fminf(y1, y2);
        const int iymax = (int)fmaxf(y1, y2);
        const int pk = iymin | ((iymax - iymin) << 16);
        edge[pv][v] = make_float4(y1, s, x1, __int_as_float(pk));
    }
    __syncthreads();

    // ---- rasterize my row of my polygon: XOR of prefix masks per edge ----
    const float py = (float)row;
    ull lo = 0, hi = 0;
#pragma unroll
    for (int v = 0; v < Vn; v++) {
        const float4 e = edge[p][v];
        const int pk = __float_as_int(e.w);
        const bool crosses = (unsigned)(row - (pk & 0xFFFF)) < (unsigned)(pk >> 16);
        const float xint = fmaf(py - e.x, e.y, e.z);
        // crossing x-intersections lie in [10,121]; m=0 -> both masks zero
        const int m = crosses ? __float2int_ru(xint) : 0;
        lo ^= shr64c(64  - min(m, 64));   // low m bits (saturating)
        hi ^= shr64c(128 - max(m, 64));   // bits [64, m)
    }

    // gt threads publish their row masks
    if (p == 1) { s_glo[row] = lo; s_ghi[row] = hi; }
    __syncthreads();

    // per-thread contributions
    int my_area  = __popcll(lo) + __popcll(hi);        // parea (p=0) or garea (p=1)
    int my_inter = 0;
    if (p == 0)
        my_inter = __popcll(lo & s_glo[row]) + __popcll(hi & s_ghi[row]);

    // ---- block reduce (256 threads = 8 warps) ----
    __shared__ int s_i[8], s_a[8];
#pragma unroll
    for (int off = 16; off > 0; off >>= 1) {
        my_inter += __shfl_down_sync(0xFFFFFFFFu, my_inter, off);
        my_area  += __shfl_down_sync(0xFFFFFFFFu, my_area,  off);
    }
    const int warp = tid >> 5;
    const int lane = tid & 31;
    if (lane == 0) { s_i[warp] = my_inter; s_a[warp] = my_area; }
    __syncthreads();

    if (tid == 0) {
        int I = 0, PG = 0;
#pragma unroll
        for (int w = 0; w < 8; w++) { I += s_i[w]; PG += s_a[w]; }
        const float interf = (float)I;
        const float unionf = (float)PG - interf;
        const float iou = interf / (unionf + 0.0001f);
        const int   m   = mask[bk];
        // 32.32 fixed point: deterministic conversion, order-independent add
        const ull fx = (ull)((double)(iou * (float)m) * 4294967296.0);
        atomicAdd(&g_num, fx);
        atomicAdd(&g_den, (unsigned int)m);
        __threadfence();                      // value adds visible before counter
        const unsigned int c = atomicAdd(&g_done, 1u);
        if (c == (unsigned int)(BKn - 1)) {
            // strong atomic reads see all prior (fenced) contributions
            const ull          n = atomicAdd(&g_num, 0ull);
            const unsigned int d = atomicAdd(&g_den, 0u);
            const float N = (float)((double)n * (1.0 / 4294967296.0));
            const float D = (float)d;
            loss[0] = 1.0f - N / (D + 0.0001f);
            // reset for next graph replay (visible at kernel completion)
            g_num  = 0ull;
            g_den  = 0u;
            g_done = 0u;
        }
    }
}

extern "C" void kernel_launch(void* const* d_in, const int* in_sizes, int n_in,
                              void* d_out, int out_size) {
    const float* out4d  = (const float*)d_in[0];   // output  [B,C,H,W]
    const int*   mask   = (const int*)  d_in[1];   // mask    [B,K]
    const int*   ind    = (const int*)  d_in[2];   // ind     [B,K]
    const float* target = (const float*)d_in[3];   // target  [B,C,K]
    float* loss = (float*)d_out;

    iou_fused_kernel<<<BKn, 256>>>(out4d, mask, ind, target, loss);
}